// round 15
// baseline (speedup 1.0000x reference)
#include <cuda_runtime.h>
#include <cuda_fp16.h>
#include <cstdint>

#define NUM_EXPERTS 8
#define HIDDEN 1024
#define NUM_TOKENS 8192

// ---------------- scratch (allocation-free: __device__ globals) -------------
__device__ int   g_count[NUM_EXPERTS];
__device__ int   g_tok[NUM_EXPERTS * NUM_TOKENS];
__device__ float g_wt [NUM_EXPERTS * NUM_TOKENS];
__device__ __half g_xh [NUM_TOKENS * HIDDEN];
__device__ __half g_ewh[NUM_EXPERTS * HIDDEN * HIDDEN];

// ---------------- helpers ----------------------------------------------------
__device__ __forceinline__ uint32_t smem_u32(const void* p) {
    uint32_t a;
    asm("{ .reg .u64 t; cvta.to.shared.u64 t, %1; cvt.u32.u64 %0, t; }"
        : "=r"(a) : "l"(p));
    return a;
}

__device__ __forceinline__ void cp16(uint32_t dst, const void* src) {
    asm volatile("cp.async.cg.shared.global [%0], [%1], 16;"
                 :: "r"(dst), "l"(src) : "memory");
}
__device__ __forceinline__ void cp_commit() {
    asm volatile("cp.async.commit_group;" ::: "memory");
}
template <int N>
__device__ __forceinline__ void cp_wait() {
    asm volatile("cp.async.wait_group %0;" :: "n"(N) : "memory");
}

__device__ __forceinline__ void ldsm4(uint32_t& r0, uint32_t& r1, uint32_t& r2,
                                      uint32_t& r3, uint32_t addr) {
    asm volatile("ldmatrix.sync.aligned.m8n8.x4.shared.b16 {%0,%1,%2,%3}, [%4];"
                 : "=r"(r0), "=r"(r1), "=r"(r2), "=r"(r3) : "r"(addr));
}

__device__ __forceinline__ void mma16816(float* c, const uint32_t* a,
                                         uint32_t b0, uint32_t b1) {
    asm volatile(
        "mma.sync.aligned.m16n8k16.row.col.f32.f16.f16.f32 "
        "{%0,%1,%2,%3}, {%4,%5,%6,%7}, {%8,%9}, {%0,%1,%2,%3};"
        : "+f"(c[0]), "+f"(c[1]), "+f"(c[2]), "+f"(c[3])
        : "r"(a[0]), "r"(a[1]), "r"(a[2]), "r"(a[3]), "r"(b0), "r"(b1));
}

// ---------------- kernel 1: fused prep (zero + convert + gate) --------------
#define XQ (NUM_TOKENS * HIDDEN / 4)
#define EQ (NUM_EXPERTS * HIDDEN * HIDDEN / 4)
#define NB_CONV ((XQ + EQ) / 256)
#define NB_GATE (NUM_TOKENS / 8)
#define WSCALE 64.0f

__global__ void prep_kernel(const float4* __restrict__ x4,
                            const float4* __restrict__ ew4,
                            float4* __restrict__ out4,
                            const float* __restrict__ x,
                            const float* __restrict__ gw) {
    __shared__ float sg[NUM_EXPERTS * HIDDEN]; // 32 KB (gate blocks only)
    int tid = threadIdx.x;

    if (blockIdx.x < NB_CONV) {
        int idx = blockIdx.x * 256 + tid;
        if (idx < 8) g_count[idx] = 0;
        if (idx < XQ) {
            out4[idx] = make_float4(0.f, 0.f, 0.f, 0.f);
            float4 v = x4[idx];
            __half2 h0, h1;
            h0.x = __float2half_rn(v.x); h0.y = __float2half_rn(v.y);
            h1.x = __float2half_rn(v.z); h1.y = __float2half_rn(v.w);
            uint2 H;
            H.x = *reinterpret_cast<uint32_t*>(&h0);
            H.y = *reinterpret_cast<uint32_t*>(&h1);
            *reinterpret_cast<uint2*>(g_xh + (size_t)idx * 4) = H;
        } else {
            int j = idx - XQ;
            float4 v = ew4[j];
            __half2 h0, h1;
            h0.x = __float2half_rn(v.x * WSCALE); h0.y = __float2half_rn(v.y * WSCALE);
            h1.x = __float2half_rn(v.z * WSCALE); h1.y = __float2half_rn(v.w * WSCALE);
            uint2 H;
            H.x = *reinterpret_cast<uint32_t*>(&h0);
            H.y = *reinterpret_cast<uint32_t*>(&h1);
            *reinterpret_cast<uint2*>(g_ewh + (size_t)j * 4) = H;
        }
        return;
    }

    int gbid = blockIdx.x - NB_CONV;
    for (int i = tid; i < NUM_EXPERTS * HIDDEN; i += 256) sg[i] = gw[i];
    __syncthreads();

    int warp = tid >> 5, lane = tid & 31;
    int t = gbid * 8 + warp;
    if (t >= NUM_TOKENS) return;

    const float* xr = x + (size_t)t * HIDDEN;
    float acc[NUM_EXPERTS];
#pragma unroll
    for (int e = 0; e < NUM_EXPERTS; e++) acc[e] = 0.f;

    for (int i = lane; i < HIDDEN; i += 32) {
        float xv = xr[i];
#pragma unroll
        for (int e = 0; e < NUM_EXPERTS; e++)
            acc[e] = fmaf(xv, sg[e * HIDDEN + i], acc[e]);
    }
#pragma unroll
    for (int e = 0; e < NUM_EXPERTS; e++) {
#pragma unroll
        for (int o = 16; o > 0; o >>= 1)
            acc[e] += __shfl_xor_sync(0xFFFFFFFFu, acc[e], o);
    }

    if (lane == 0) {
        float m = acc[0];
#pragma unroll
        for (int e = 1; e < NUM_EXPERTS; e++) m = fmaxf(m, acc[e]);
        float p[NUM_EXPERTS], s = 0.f;
#pragma unroll
        for (int e = 0; e < NUM_EXPERTS; e++) { p[e] = __expf(acc[e] - m); s += p[e]; }
        float inv = 1.f / s;
#pragma unroll
        for (int e = 0; e < NUM_EXPERTS; e++) p[e] *= inv;

        int i1 = 0;
#pragma unroll
        for (int e = 1; e < NUM_EXPERTS; e++) if (p[e] > p[i1]) i1 = e;
        int i2 = (i1 == 0) ? 1 : 0;
#pragma unroll
        for (int e = 0; e < NUM_EXPERTS; e++)
            if (e != i1 && p[e] > p[i2]) i2 = e;

        int pos1 = atomicAdd(&g_count[i1], 1);
        g_tok[i1 * NUM_TOKENS + pos1] = t;
        g_wt [i1 * NUM_TOKENS + pos1] = p[i1];
        int pos2 = atomicAdd(&g_count[i2], 1);
        g_tok[i2 * NUM_TOKENS + pos2] = t;
        g_wt [i2 * NUM_TOKENS + pos2] = p[i2];
    }
}

// ---------------- kernel 2: HMMA GEMM, small decoupled CTAs -----------------
// CTA: 128(M) x 128(N), 128 threads, 4 warps in 2(M) x 2(N), warp tile 64x64.
// BK=64, 2 stages, 1 sync/chunk. Per k-step: 8 LDSM.x4 -> 32 HMMA (ratio 4).
// 2 CTAs/SM -> two independent barrier domains overlap each other's stalls.
#define BK    64
#define NC    (HIDDEN / BK)      // 16 chunks
#define ROWB  144                // 128 B data + 16 B pad (conflict-free)
#define SM_B  (128 * ROWB)       // 18432: B rows (A at 0)
#define STG   (256 * ROWB)       // 36864 bytes per stage
#define SMEM_DYN (2 * STG)       // 73728

__global__ __launch_bounds__(128, 2) void moe_hmma_kernel(float* __restrict__ out) {
    int e = blockIdx.z;
    int cnt = g_count[e];
    int m0 = blockIdx.y * 128;
    if (m0 >= cnt) return;
    int n0 = blockIdx.x * 128;

    extern __shared__ __align__(16) char sm[];
    __shared__ int   s_tok[128];
    __shared__ float s_wgt[128];

    int tid = threadIdx.x, wid = tid >> 5, lane = tid & 31;
    uint32_t sb = smem_u32(sm);

    {
        int m = m0 + tid;
        int tok = -1; float wv = 0.f;
        if (m < cnt) {
            tok = g_tok[e * NUM_TOKENS + m];
            wv  = g_wt [e * NUM_TOKENS + m];
        }
        s_tok[tid] = tok;
        s_wgt[tid] = wv * (1.0f / WSCALE);
    }
    __syncthreads();

    // ---- loader mapping: each thread loads A row tid AND B row tid ----------
    const __half* pA;
    {
        int tok = s_tok[tid];
        pA = g_xh + (size_t)(tok >= 0 ? tok : 0) * HIDDEN;
    }
    const __half* pB = g_ewh + ((size_t)e * HIDDEN + n0 + tid) * HIDDEN;
    uint32_t dA = sb + (uint32_t)tid * ROWB;
    uint32_t dB = sb + SM_B + (uint32_t)tid * ROWB;

    // ---- compute mapping -----------------------------------------------------
    int warp_m = wid & 1;        // 0..1 (64 rows each)
    int warp_n = wid >> 1;       // 0..1 (64 cols each)

    uint32_t a_lane_off = (uint32_t)((lane & 15) * ROWB + (lane >> 4) * 16)
                        + (uint32_t)(warp_m * 64 * ROWB);
    uint32_t b_lane_off = (uint32_t)((((lane >> 4) * 8) + (lane & 7)) * ROWB
                                     + ((lane >> 3) & 1) * 16)
                        + SM_B + (uint32_t)(warp_n * 64 * ROWB);

    float acc[4][8][4];
#pragma unroll
    for (int i = 0; i < 4; i++)
#pragma unroll
        for (int j = 0; j < 8; j++)
#pragma unroll
            for (int q = 0; q < 4; q++) acc[i][j][q] = 0.f;

    // ---- prologue: stage chunk 0 (8 cp16 per row, both rows) ------------------
    {
#pragma unroll
        for (int j = 0; j < 8; j++) cp16(dA + j * 16, pA + j * 8);
#pragma unroll
        for (int j = 0; j < 8; j++) cp16(dB + j * 16, pB + j * 8);
        cp_commit();
    }

    for (int c = 0; c < NC; c++) {
        cp_wait<0>();
        __syncthreads();

        if (c + 1 < NC) {
            uint32_t soff = (uint32_t)(((c + 1) & 1) * STG);
            const __half* qA = pA + (c + 1) * BK;
            const __half* qB = pB + (c + 1) * BK;
#pragma unroll
            for (int j = 0; j < 8; j++) cp16(dA + soff + j * 16, qA + j * 8);
#pragma unroll
            for (int j = 0; j < 8; j++) cp16(dB + soff + j * 16, qB + j * 8);
            cp_commit();
        }

        uint32_t stb = sb + (uint32_t)((c & 1) * STG);
        uint32_t aH = stb + a_lane_off;
        uint32_t bH = stb + b_lane_off;

#pragma unroll
        for (int ks = 0; ks < 4; ks++) {
            uint32_t ko = (uint32_t)(ks * 32);  // 16 fp16 = 32 B

            uint32_t ah[4][4], bh[4][4];
#pragma unroll
            for (int mf = 0; mf < 4; mf++)
                ldsm4(ah[mf][0], ah[mf][1], ah[mf][2], ah[mf][3],
                      aH + mf * 16 * ROWB + ko);
#pragma unroll
            for (int bf = 0; bf < 4; bf++)
                ldsm4(bh[bf][0], bh[bf][1], bh[bf][2], bh[bf][3],
                      bH + bf * 16 * ROWB + ko);

#pragma unroll
            for (int mf = 0; mf < 4; mf++)
#pragma unroll
                for (int nf = 0; nf < 8; nf++)
                    mma16816(acc[mf][nf], ah[mf],
                             bh[nf >> 1][(nf & 1) * 2], bh[nf >> 1][(nf & 1) * 2 + 1]);
        }
    }

    // ---- epilogue: weight-scaled float2 atomic scatter ------------------------
    int tq  = lane >> 2;
    int tc2 = (lane & 3) * 2;
#pragma unroll
    for (int mf = 0; mf < 4; mf++) {
        int r0 = warp_m * 64 + mf * 16 + tq;
        int t0 = s_tok[r0];
        int t1 = s_tok[r0 + 8];
        float w0 = s_wgt[r0];
        float w1 = s_wgt[r0 + 8];
        float* o0 = (t0 >= 0) ? out + (size_t)t0 * HIDDEN : nullptr;
        float* o1 = (t1 >= 0) ? out + (size_t)t1 * HIDDEN : nullptr;
#pragma unroll
        for (int nf = 0; nf < 8; nf++) {
            int col = n0 + warp_n * 64 + nf * 8 + tc2;
            if (o0)
                atomicAdd(reinterpret_cast<float2*>(o0 + col),
                          make_float2(w0 * acc[mf][nf][0], w0 * acc[mf][nf][1]));
            if (o1)
                atomicAdd(reinterpret_cast<float2*>(o1 + col),
                          make_float2(w1 * acc[mf][nf][2], w1 * acc[mf][nf][3]));
        }
    }
}

// ---------------- launch ------------------------------------------------------
extern "C" void kernel_launch(void* const* d_in, const int* in_sizes, int n_in,
                              void* d_out, int out_size) {
    const float* x  = (const float*)d_in[0];   // [8192,1024]
    const float* gw = (const float*)d_in[1];   // [8,1024]
    const float* ew = (const float*)d_in[2];   // [8,1024,1024]
    float* out = (float*)d_out;                // [8192,1024]

    cudaFuncSetAttribute(moe_hmma_kernel,
                         cudaFuncAttributeMaxDynamicSharedMemorySize, SMEM_DYN);

    prep_kernel<<<NB_CONV + NB_GATE, 256>>>((const float4*)x, (const float4*)ew,
                                            (float4*)out, x, gw);

    dim3 grid(HIDDEN / 128, NUM_TOKENS / 128, NUM_EXPERTS);
    moe_hmma_kernel<<<grid, 128, SMEM_DYN>>>(out);
}

// round 16
// speedup vs baseline: 1.0611x; 1.0611x over previous
#include <cuda_runtime.h>
#include <cuda_fp16.h>
#include <cstdint>

#define NUM_EXPERTS 8
#define HIDDEN 1024
#define NUM_TOKENS 8192

// ---------------- scratch (allocation-free: __device__ globals) -------------
__device__ int   g_count[NUM_EXPERTS];
__device__ int   g_tok[NUM_EXPERTS * NUM_TOKENS];
__device__ float g_wt [NUM_EXPERTS * NUM_TOKENS];
__device__ __half g_xh [NUM_TOKENS * HIDDEN];
__device__ __half g_ewh[NUM_EXPERTS * HIDDEN * HIDDEN];

// ---------------- helpers ----------------------------------------------------
__device__ __forceinline__ uint32_t smem_u32(const void* p) {
    uint32_t a;
    asm("{ .reg .u64 t; cvta.to.shared.u64 t, %1; cvt.u32.u64 %0, t; }"
        : "=r"(a) : "l"(p));
    return a;
}

__device__ __forceinline__ void cp16(uint32_t dst, const void* src) {
    asm volatile("cp.async.cg.shared.global [%0], [%1], 16;"
                 :: "r"(dst), "l"(src) : "memory");
}
__device__ __forceinline__ void cp_commit() {
    asm volatile("cp.async.commit_group;" ::: "memory");
}
template <int N>
__device__ __forceinline__ void cp_wait() {
    asm volatile("cp.async.wait_group %0;" :: "n"(N) : "memory");
}

__device__ __forceinline__ void ldsm4(uint32_t& r0, uint32_t& r1, uint32_t& r2,
                                      uint32_t& r3, uint32_t addr) {
    asm volatile("ldmatrix.sync.aligned.m8n8.x4.shared.b16 {%0,%1,%2,%3}, [%4];"
                 : "=r"(r0), "=r"(r1), "=r"(r2), "=r"(r3) : "r"(addr));
}

__device__ __forceinline__ void mma16816(float* c, const uint32_t* a,
                                         uint32_t b0, uint32_t b1) {
    asm volatile(
        "mma.sync.aligned.m16n8k16.row.col.f32.f16.f16.f32 "
        "{%0,%1,%2,%3}, {%4,%5,%6,%7}, {%8,%9}, {%0,%1,%2,%3};"
        : "+f"(c[0]), "+f"(c[1]), "+f"(c[2]), "+f"(c[3])
        : "r"(a[0]), "r"(a[1]), "r"(a[2]), "r"(a[3]), "r"(b0), "r"(b1));
}

// ---------------- kernel 1: fused prep ---------------------------------------
// ew blocks: fp32 -> fp16 (x WSCALE), 4 float4 per thread (MLP=4)
// gate blocks: logits + top2 dispatch + x fp32->fp16 + out zeroing
#define XQ (NUM_TOKENS * HIDDEN / 4)
#define EQ (NUM_EXPERTS * HIDDEN * HIDDEN / 4)
#define COARSE 4
#define NB_EW (EQ / (256 * COARSE))     // 2048 blocks
#define NB_GATE (NUM_TOKENS / 8)        // 1024 blocks
#define WSCALE 64.0f

__global__ void prep_kernel(const float4* __restrict__ x4,
                            const float4* __restrict__ ew4,
                            float4* __restrict__ out4,
                            const float* __restrict__ gw) {
    __shared__ float sg[NUM_EXPERTS * HIDDEN]; // 32 KB (gate blocks only)
    int tid = threadIdx.x;

    if (blockIdx.x < NB_EW) {
        // ------- ew convert: 4 independent float4s per thread ----------------
        int base = blockIdx.x * 256 * COARSE + tid;
        if (blockIdx.x == 0 && tid < 8) g_count[tid] = 0;
        float4 v[COARSE];
#pragma unroll
        for (int k = 0; k < COARSE; k++) v[k] = ew4[base + k * 256];
#pragma unroll
        for (int k = 0; k < COARSE; k++) {
            int j = base + k * 256;
            __half2 h0, h1;
            h0.x = __float2half_rn(v[k].x * WSCALE); h0.y = __float2half_rn(v[k].y * WSCALE);
            h1.x = __float2half_rn(v[k].z * WSCALE); h1.y = __float2half_rn(v[k].w * WSCALE);
            uint2 H;
            H.x = *reinterpret_cast<uint32_t*>(&h0);
            H.y = *reinterpret_cast<uint32_t*>(&h1);
            *reinterpret_cast<uint2*>(g_ewh + (size_t)j * 4) = H;
        }
        return;
    }

    // ------- gate: logits + dispatch + x convert + out zero -------------------
    int gbid = blockIdx.x - NB_EW;
    for (int i = tid; i < NUM_EXPERTS * HIDDEN; i += 256) sg[i] = gw[i];
    __syncthreads();

    int warp = tid >> 5, lane = tid & 31;
    int t = gbid * 8 + warp;
    if (t >= NUM_TOKENS) return;

    const float4* xr4 = x4 + (size_t)t * (HIDDEN / 4);
    float acc[NUM_EXPERTS];
#pragma unroll
    for (int e = 0; e < NUM_EXPERTS; e++) acc[e] = 0.f;

    const float4 z4 = make_float4(0.f, 0.f, 0.f, 0.f);
    for (int i = lane; i < HIDDEN / 4; i += 32) {
        float4 v = xr4[i];
        // convert x -> fp16 (single read serves both gate + conversion)
        __half2 h0, h1;
        h0.x = __float2half_rn(v.x); h0.y = __float2half_rn(v.y);
        h1.x = __float2half_rn(v.z); h1.y = __float2half_rn(v.w);
        uint2 H;
        H.x = *reinterpret_cast<uint32_t*>(&h0);
        H.y = *reinterpret_cast<uint32_t*>(&h1);
        *reinterpret_cast<uint2*>(g_xh + (size_t)t * HIDDEN + i * 4) = H;
        // zero the output row
        out4[(size_t)t * (HIDDEN / 4) + i] = z4;
        // logits
#pragma unroll
        for (int e = 0; e < NUM_EXPERTS; e++) {
            const float* sge = sg + e * HIDDEN + i * 4;
            acc[e] = fmaf(v.x, sge[0], acc[e]);
            acc[e] = fmaf(v.y, sge[1], acc[e]);
            acc[e] = fmaf(v.z, sge[2], acc[e]);
            acc[e] = fmaf(v.w, sge[3], acc[e]);
        }
    }
#pragma unroll
    for (int e = 0; e < NUM_EXPERTS; e++) {
#pragma unroll
        for (int o = 16; o > 0; o >>= 1)
            acc[e] += __shfl_xor_sync(0xFFFFFFFFu, acc[e], o);
    }

    if (lane == 0) {
        float m = acc[0];
#pragma unroll
        for (int e = 1; e < NUM_EXPERTS; e++) m = fmaxf(m, acc[e]);
        float p[NUM_EXPERTS], s = 0.f;
#pragma unroll
        for (int e = 0; e < NUM_EXPERTS; e++) { p[e] = __expf(acc[e] - m); s += p[e]; }
        float inv = 1.f / s;
#pragma unroll
        for (int e = 0; e < NUM_EXPERTS; e++) p[e] *= inv;

        int i1 = 0;
#pragma unroll
        for (int e = 1; e < NUM_EXPERTS; e++) if (p[e] > p[i1]) i1 = e;
        int i2 = (i1 == 0) ? 1 : 0;
#pragma unroll
        for (int e = 0; e < NUM_EXPERTS; e++)
            if (e != i1 && p[e] > p[i2]) i2 = e;

        int pos1 = atomicAdd(&g_count[i1], 1);
        g_tok[i1 * NUM_TOKENS + pos1] = t;
        g_wt [i1 * NUM_TOKENS + pos1] = p[i1];
        int pos2 = atomicAdd(&g_count[i2], 1);
        g_tok[i2 * NUM_TOKENS + pos2] = t;
        g_wt [i2 * NUM_TOKENS + pos2] = p[i2];
    }
}

// ---------------- kernel 2: HMMA GEMM (R12 champion config, unchanged) ------
// CTA: 128 x 128, 8 warps in 2(M) x 4(N), warp tile 64x32. BK=64, 2 stages,
// 1 sync/chunk, fragment double-buffering. smem-crossbar-bound at ~184 us.
#define BK    64
#define NC    (HIDDEN / BK)      // 16 chunks
#define ROWB  144                // 128 B data + 16 B pad (conflict-free)
#define SM_B  (128 * ROWB)       // 18432: B (A at 0)
#define STG   (2 * 128 * ROWB)   // 36864 bytes per stage
#define SMEM_DYN (2 * STG)       // 73728

__global__ __launch_bounds__(256, 2) void moe_hmma_kernel(float* __restrict__ out) {
    int e = blockIdx.z;
    int cnt = g_count[e];
    int m0 = blockIdx.y * 128;
    if (m0 >= cnt) return;
    int n0 = blockIdx.x * 128;

    extern __shared__ __align__(16) char sm[];
    __shared__ int   s_tok[128];
    __shared__ float s_wgt[128];

    int tid = threadIdx.x, wid = tid >> 5, lane = tid & 31;
    uint32_t sb = smem_u32(sm);

    if (tid < 128) {
        int m = m0 + tid;
        int tok = -1; float wv = 0.f;
        if (m < cnt) {
            tok = g_tok[e * NUM_TOKENS + m];
            wv  = g_wt [e * NUM_TOKENS + m];
        }
        s_tok[tid] = tok;
        s_wgt[tid] = wv * (1.0f / WSCALE);
    }
    __syncthreads();

    // ---- loader mapping: threads 0..127 -> A rows; 128..255 -> B rows -------
    int  row = tid & 127;
    bool isB = (tid >= 128);
    const __half* p0;
    if (isB) {
        p0 = g_ewh + ((size_t)e * HIDDEN + n0 + row) * HIDDEN;
    } else {
        int tok = s_tok[row];
        p0 = g_xh + (size_t)(tok >= 0 ? tok : 0) * HIDDEN;
    }
    uint32_t d0 = sb + (isB ? SM_B : 0) + (uint32_t)row * ROWB;

    // ---- compute mapping -----------------------------------------------------
    int warp_m = wid & 1;        // 0..1 (64 rows each)
    int warp_n = wid >> 1;       // 0..3 (32 cols each)

    uint32_t a_lane_off = (uint32_t)((lane & 15) * ROWB + (lane >> 4) * 16)
                        + (uint32_t)(warp_m * 64 * ROWB);
    uint32_t b_lane_off = (uint32_t)((((lane >> 4) * 8) + (lane & 7)) * ROWB
                                     + ((lane >> 3) & 1) * 16)
                        + SM_B + (uint32_t)(warp_n * 32 * ROWB);

    float acc[4][4][4];
#pragma unroll
    for (int i = 0; i < 4; i++)
#pragma unroll
        for (int j = 0; j < 4; j++)
#pragma unroll
            for (int q = 0; q < 4; q++) acc[i][j][q] = 0.f;

    // ---- prologue: stage chunk 0 (8 x cp16 = 128 B per row) -------------------
    {
#pragma unroll
        for (int j = 0; j < 8; j++) cp16(d0 + j * 16, p0 + j * 8);
        cp_commit();
    }

    for (int c = 0; c < NC; c++) {
        cp_wait<0>();
        __syncthreads();

        if (c + 1 < NC) {
            uint32_t soff = (uint32_t)(((c + 1) & 1) * STG);
            const __half* q0 = p0 + (c + 1) * BK;
#pragma unroll
            for (int j = 0; j < 8; j++) cp16(d0 + soff + j * 16, q0 + j * 8);
            cp_commit();
        }

        uint32_t stb = sb + (uint32_t)((c & 1) * STG);
        uint32_t aH = stb + a_lane_off;
        uint32_t bH = stb + b_lane_off;

        // ---- fragment double-buffer across 4 k-steps --------------------------
        uint32_t ah[2][4][4], bh[2][2][4];

#pragma unroll
        for (int mf = 0; mf < 4; mf++)
            ldsm4(ah[0][mf][0], ah[0][mf][1], ah[0][mf][2], ah[0][mf][3],
                  aH + mf * 16 * ROWB);
#pragma unroll
        for (int bf = 0; bf < 2; bf++)
            ldsm4(bh[0][bf][0], bh[0][bf][1], bh[0][bf][2], bh[0][bf][3],
                  bH + bf * 16 * ROWB);

#pragma unroll
        for (int ks = 0; ks < 4; ks++) {
            int cur = ks & 1, nxt = cur ^ 1;
            if (ks < 3) {
                uint32_t ko = (uint32_t)((ks + 1) * 32);
#pragma unroll
                for (int mf = 0; mf < 4; mf++)
                    ldsm4(ah[nxt][mf][0], ah[nxt][mf][1], ah[nxt][mf][2], ah[nxt][mf][3],
                          aH + mf * 16 * ROWB + ko);
#pragma unroll
                for (int bf = 0; bf < 2; bf++)
                    ldsm4(bh[nxt][bf][0], bh[nxt][bf][1], bh[nxt][bf][2], bh[nxt][bf][3],
                          bH + bf * 16 * ROWB + ko);
            }
#pragma unroll
            for (int mf = 0; mf < 4; mf++)
#pragma unroll
                for (int nf = 0; nf < 4; nf++)
                    mma16816(acc[mf][nf], ah[cur][mf],
                             bh[cur][nf >> 1][(nf & 1) * 2],
                             bh[cur][nf >> 1][(nf & 1) * 2 + 1]);
        }
    }

    // ---- epilogue: weight-scaled float2 atomic scatter ------------------------
    int tq  = lane >> 2;
    int tc2 = (lane & 3) * 2;
#pragma unroll
    for (int mf = 0; mf < 4; mf++) {
        int r0 = warp_m * 64 + mf * 16 + tq;
        int t0 = s_tok[r0];
        int t1 = s_tok[r0 + 8];
        float w0 = s_wgt[r0];
        float w1 = s_wgt[r0 + 8];
        float* o0 = (t0 >= 0) ? out + (size_t)t0 * HIDDEN : nullptr;
        float* o1 = (t1 >= 0) ? out + (size_t)t1 * HIDDEN : nullptr;
#pragma unroll
        for (int nf = 0; nf < 4; nf++) {
            int col = n0 + warp_n * 32 + nf * 8 + tc2;
            if (o0)
                atomicAdd(reinterpret_cast<float2*>(o0 + col),
                          make_float2(w0 * acc[mf][nf][0], w0 * acc[mf][nf][1]));
            if (o1)
                atomicAdd(reinterpret_cast<float2*>(o1 + col),
                          make_float2(w1 * acc[mf][nf][2], w1 * acc[mf][nf][3]));
        }
    }
}

// ---------------- launch ------------------------------------------------------
extern "C" void kernel_launch(void* const* d_in, const int* in_sizes, int n_in,
                              void* d_out, int out_size) {
    const float* x  = (const float*)d_in[0];   // [8192,1024]
    const float* gw = (const float*)d_in[1];   // [8,1024]
    const float* ew = (const float*)d_in[2];   // [8,1024,1024]
    float* out = (float*)d_out;                // [8192,1024]

    cudaFuncSetAttribute(moe_hmma_kernel,
                         cudaFuncAttributeMaxDynamicSharedMemorySize, SMEM_DYN);

    prep_kernel<<<NB_EW + NB_GATE, 256>>>((const float4*)x, (const float4*)ew,
                                          (float4*)out, gw);

    dim3 grid(HIDDEN / 128, NUM_TOKENS / 128, NUM_EXPERTS);
    moe_hmma_kernel<<<grid, 256, SMEM_DYN>>>(out);
}

// round 17
// speedup vs baseline: 1.0620x; 1.0008x over previous
#include <cuda_runtime.h>
#include <cuda_fp16.h>
#include <cstdint>

#define NUM_EXPERTS 8
#define HIDDEN 1024
#define NUM_TOKENS 8192

// ---------------- scratch (allocation-free: __device__ globals) -------------
__device__ int   g_count[NUM_EXPERTS];
__device__ int   g_tok[NUM_EXPERTS * NUM_TOKENS];
__device__ float g_wt [NUM_EXPERTS * NUM_TOKENS];
__device__ __half g_xh [NUM_TOKENS * HIDDEN];
__device__ __half g_ewh[NUM_EXPERTS * HIDDEN * HIDDEN];

// ---------------- helpers ----------------------------------------------------
__device__ __forceinline__ uint32_t smem_u32(const void* p) {
    uint32_t a;
    asm("{ .reg .u64 t; cvta.to.shared.u64 t, %1; cvt.u32.u64 %0, t; }"
        : "=r"(a) : "l"(p));
    return a;
}

__device__ __forceinline__ void cp16(uint32_t dst, const void* src) {
    asm volatile("cp.async.cg.shared.global [%0], [%1], 16;"
                 :: "r"(dst), "l"(src) : "memory");
}
__device__ __forceinline__ void cp_commit() {
    asm volatile("cp.async.commit_group;" ::: "memory");
}
template <int N>
__device__ __forceinline__ void cp_wait() {
    asm volatile("cp.async.wait_group %0;" :: "n"(N) : "memory");
}

__device__ __forceinline__ void ldsm4(uint32_t& r0, uint32_t& r1, uint32_t& r2,
                                      uint32_t& r3, uint32_t addr) {
    asm volatile("ldmatrix.sync.aligned.m8n8.x4.shared.b16 {%0,%1,%2,%3}, [%4];"
                 : "=r"(r0), "=r"(r1), "=r"(r2), "=r"(r3) : "r"(addr));
}

__device__ __forceinline__ void mma16816(float* c, const uint32_t* a,
                                         uint32_t b0, uint32_t b1) {
    asm volatile(
        "mma.sync.aligned.m16n8k16.row.col.f32.f16.f16.f32 "
        "{%0,%1,%2,%3}, {%4,%5,%6,%7}, {%8,%9}, {%0,%1,%2,%3};"
        : "+f"(c[0]), "+f"(c[1]), "+f"(c[2]), "+f"(c[3])
        : "r"(a[0]), "r"(a[1]), "r"(a[2]), "r"(a[3]), "r"(b0), "r"(b1));
}

__device__ __forceinline__ uint32_t cvt2(float a, float b) {
    __half2 h;
    h.x = __float2half_rn(a);
    h.y = __float2half_rn(b);
    return *reinterpret_cast<uint32_t*>(&h);
}

// ---------------- kernel 1: fused prep ---------------------------------------
// ew blocks: fp32 -> fp16 (x WSCALE), 4 CONSECUTIVE float4 per thread
//            (MLP=4 loads, 2x 16B coalesced stores)
// gate blocks: logits + top2 dispatch + x fp32->fp16 + out zeroing
#define XQ (NUM_TOKENS * HIDDEN / 4)
#define EQ (NUM_EXPERTS * HIDDEN * HIDDEN / 4)
#define COARSE 4
#define NB_EW (EQ / (256 * COARSE))     // 2048 blocks
#define NB_GATE (NUM_TOKENS / 8)        // 1024 blocks
#define WSCALE 64.0f

__global__ void prep_kernel(const float4* __restrict__ x4,
                            const float4* __restrict__ ew4,
                            float4* __restrict__ out4,
                            const float* __restrict__ gw) {
    __shared__ float sg[NUM_EXPERTS * HIDDEN]; // 32 KB (gate blocks only)
    int tid = threadIdx.x;

    if (blockIdx.x < NB_EW) {
        // ------- ew convert: 4 consecutive float4s per thread -----------------
        if (blockIdx.x == 0 && tid < 8) g_count[tid] = 0;
        int base = blockIdx.x * 256 * COARSE + tid * COARSE;   // float4 index
        float4 v[COARSE];
#pragma unroll
        for (int k = 0; k < COARSE; k++) v[k] = ew4[base + k];
        uint4 o0, o1;
        o0.x = cvt2(v[0].x * WSCALE, v[0].y * WSCALE);
        o0.y = cvt2(v[0].z * WSCALE, v[0].w * WSCALE);
        o0.z = cvt2(v[1].x * WSCALE, v[1].y * WSCALE);
        o0.w = cvt2(v[1].z * WSCALE, v[1].w * WSCALE);
        o1.x = cvt2(v[2].x * WSCALE, v[2].y * WSCALE);
        o1.y = cvt2(v[2].z * WSCALE, v[2].w * WSCALE);
        o1.z = cvt2(v[3].x * WSCALE, v[3].y * WSCALE);
        o1.w = cvt2(v[3].z * WSCALE, v[3].w * WSCALE);
        uint4* dst = reinterpret_cast<uint4*>(g_ewh + (size_t)base * 4);
        dst[0] = o0;
        dst[1] = o1;
        return;
    }

    // ------- gate: logits + dispatch + x convert + out zero -------------------
    int gbid = blockIdx.x - NB_EW;
    for (int i = tid; i < NUM_EXPERTS * HIDDEN; i += 256) sg[i] = gw[i];
    __syncthreads();

    int warp = tid >> 5, lane = tid & 31;
    int t = gbid * 8 + warp;
    if (t >= NUM_TOKENS) return;

    const float4* xr4 = x4 + (size_t)t * (HIDDEN / 4);
    float acc[NUM_EXPERTS];
#pragma unroll
    for (int e = 0; e < NUM_EXPERTS; e++) acc[e] = 0.f;

    const float4 z4 = make_float4(0.f, 0.f, 0.f, 0.f);
    for (int i = lane; i < HIDDEN / 4; i += 32) {
        float4 v = xr4[i];
        // convert x -> fp16 (single read serves gate + conversion)
        uint2 H;
        H.x = cvt2(v.x, v.y);
        H.y = cvt2(v.z, v.w);
        *reinterpret_cast<uint2*>(g_xh + (size_t)t * HIDDEN + i * 4) = H;
        // zero the output row
        out4[(size_t)t * (HIDDEN / 4) + i] = z4;
        // logits
#pragma unroll
        for (int e = 0; e < NUM_EXPERTS; e++) {
            const float* sge = sg + e * HIDDEN + i * 4;
            acc[e] = fmaf(v.x, sge[0], acc[e]);
            acc[e] = fmaf(v.y, sge[1], acc[e]);
            acc[e] = fmaf(v.z, sge[2], acc[e]);
            acc[e] = fmaf(v.w, sge[3], acc[e]);
        }
    }
#pragma unroll
    for (int e = 0; e < NUM_EXPERTS; e++) {
#pragma unroll
        for (int o = 16; o > 0; o >>= 1)
            acc[e] += __shfl_xor_sync(0xFFFFFFFFu, acc[e], o);
    }

    if (lane == 0) {
        float m = acc[0];
#pragma unroll
        for (int e = 1; e < NUM_EXPERTS; e++) m = fmaxf(m, acc[e]);
        float p[NUM_EXPERTS], s = 0.f;
#pragma unroll
        for (int e = 0; e < NUM_EXPERTS; e++) { p[e] = __expf(acc[e] - m); s += p[e]; }
        float inv = 1.f / s;
#pragma unroll
        for (int e = 0; e < NUM_EXPERTS; e++) p[e] *= inv;

        int i1 = 0;
#pragma unroll
        for (int e = 1; e < NUM_EXPERTS; e++) if (p[e] > p[i1]) i1 = e;
        int i2 = (i1 == 0) ? 1 : 0;
#pragma unroll
        for (int e = 0; e < NUM_EXPERTS; e++)
            if (e != i1 && p[e] > p[i2]) i2 = e;

        int pos1 = atomicAdd(&g_count[i1], 1);
        g_tok[i1 * NUM_TOKENS + pos1] = t;
        g_wt [i1 * NUM_TOKENS + pos1] = p[i1];
        int pos2 = atomicAdd(&g_count[i2], 1);
        g_tok[i2 * NUM_TOKENS + pos2] = t;
        g_wt [i2 * NUM_TOKENS + pos2] = p[i2];
    }
}

// ---------------- kernel 2: HMMA GEMM (champion config, unchanged) ----------
// CTA: 128 x 128, 8 warps in 2(M) x 4(N), warp tile 64x32. BK=64, 2 stages,
// 1 sync/chunk, fragment double-buffering. smem-traffic-bound at ~185 us.
#define BK    64
#define NC    (HIDDEN / BK)      // 16 chunks
#define ROWB  144                // 128 B data + 16 B pad (conflict-free)
#define SM_B  (128 * ROWB)       // 18432: B (A at 0)
#define STG   (2 * 128 * ROWB)   // 36864 bytes per stage
#define SMEM_DYN (2 * STG)       // 73728

__global__ __launch_bounds__(256, 2) void moe_hmma_kernel(float* __restrict__ out) {
    int e = blockIdx.z;
    int cnt = g_count[e];
    int m0 = blockIdx.y * 128;
    if (m0 >= cnt) return;
    int n0 = blockIdx.x * 128;

    extern __shared__ __align__(16) char sm[];
    __shared__ int   s_tok[128];
    __shared__ float s_wgt[128];

    int tid = threadIdx.x, wid = tid >> 5, lane = tid & 31;
    uint32_t sb = smem_u32(sm);

    if (tid < 128) {
        int m = m0 + tid;
        int tok = -1; float wv = 0.f;
        if (m < cnt) {
            tok = g_tok[e * NUM_TOKENS + m];
            wv  = g_wt [e * NUM_TOKENS + m];
        }
        s_tok[tid] = tok;
        s_wgt[tid] = wv * (1.0f / WSCALE);
    }
    __syncthreads();

    // ---- loader mapping: threads 0..127 -> A rows; 128..255 -> B rows -------
    int  row = tid & 127;
    bool isB = (tid >= 128);
    const __half* p0;
    if (isB) {
        p0 = g_ewh + ((size_t)e * HIDDEN + n0 + row) * HIDDEN;
    } else {
        int tok = s_tok[row];
        p0 = g_xh + (size_t)(tok >= 0 ? tok : 0) * HIDDEN;
    }
    uint32_t d0 = sb + (isB ? SM_B : 0) + (uint32_t)row * ROWB;

    // ---- compute mapping -----------------------------------------------------
    int warp_m = wid & 1;        // 0..1 (64 rows each)
    int warp_n = wid >> 1;       // 0..3 (32 cols each)

    uint32_t a_lane_off = (uint32_t)((lane & 15) * ROWB + (lane >> 4) * 16)
                        + (uint32_t)(warp_m * 64 * ROWB);
    uint32_t b_lane_off = (uint32_t)((((lane >> 4) * 8) + (lane & 7)) * ROWB
                                     + ((lane >> 3) & 1) * 16)
                        + SM_B + (uint32_t)(warp_n * 32 * ROWB);

    float acc[4][4][4];
#pragma unroll
    for (int i = 0; i < 4; i++)
#pragma unroll
        for (int j = 0; j < 4; j++)
#pragma unroll
            for (int q = 0; q < 4; q++) acc[i][j][q] = 0.f;

    // ---- prologue: stage chunk 0 (8 x cp16 = 128 B per row) -------------------
    {
#pragma unroll
        for (int j = 0; j < 8; j++) cp16(d0 + j * 16, p0 + j * 8);
        cp_commit();
    }

    for (int c = 0; c < NC; c++) {
        cp_wait<0>();
        __syncthreads();

        if (c + 1 < NC) {
            uint32_t soff = (uint32_t)(((c + 1) & 1) * STG);
            const __half* q0 = p0 + (c + 1) * BK;
#pragma unroll
            for (int j = 0; j < 8; j++) cp16(d0 + soff + j * 16, q0 + j * 8);
            cp_commit();
        }

        uint32_t stb = sb + (uint32_t)((c & 1) * STG);
        uint32_t aH = stb + a_lane_off;
        uint32_t bH = stb + b_lane_off;

        // ---- fragment double-buffer across 4 k-steps --------------------------
        uint32_t ah[2][4][4], bh[2][2][4];

#pragma unroll
        for (int mf = 0; mf < 4; mf++)
            ldsm4(ah[0][mf][0], ah[0][mf][1], ah[0][mf][2], ah[0][mf][3],
                  aH + mf * 16 * ROWB);
#pragma unroll
        for (int bf = 0; bf < 2; bf++)
            ldsm4(bh[0][bf][0], bh[0][bf][1], bh[0][bf][2], bh[0][bf][3],
                  bH + bf * 16 * ROWB);

#pragma unroll
        for (int ks = 0; ks < 4; ks++) {
            int cur = ks & 1, nxt = cur ^ 1;
            if (ks < 3) {
                uint32_t ko = (uint32_t)((ks + 1) * 32);
#pragma unroll
                for (int mf = 0; mf < 4; mf++)
                    ldsm4(ah[nxt][mf][0], ah[nxt][mf][1], ah[nxt][mf][2], ah[nxt][mf][3],
                          aH + mf * 16 * ROWB + ko);
#pragma unroll
                for (int bf = 0; bf < 2; bf++)
                    ldsm4(bh[nxt][bf][0], bh[nxt][bf][1], bh[nxt][bf][2], bh[nxt][bf][3],
                          bH + bf * 16 * ROWB + ko);
            }
#pragma unroll
            for (int mf = 0; mf < 4; mf++)
#pragma unroll
                for (int nf = 0; nf < 4; nf++)
                    mma16816(acc[mf][nf], ah[cur][mf],
                             bh[cur][nf >> 1][(nf & 1) * 2],
                             bh[cur][nf >> 1][(nf & 1) * 2 + 1]);
        }
    }

    // ---- epilogue: weight-scaled float2 atomic scatter ------------------------
    int tq  = lane >> 2;
    int tc2 = (lane & 3) * 2;
#pragma unroll
    for (int mf = 0; mf < 4; mf++) {
        int r0 = warp_m * 64 + mf * 16 + tq;
        int t0 = s_tok[r0];
        int t1 = s_tok[r0 + 8];
        float w0 = s_wgt[r0];
        float w1 = s_wgt[r0 + 8];
        float* o0 = (t0 >= 0) ? out + (size_t)t0 * HIDDEN : nullptr;
        float* o1 = (t1 >= 0) ? out + (size_t)t1 * HIDDEN : nullptr;
#pragma unroll
        for (int nf = 0; nf < 4; nf++) {
            int col = n0 + warp_n * 32 + nf * 8 + tc2;
            if (o0)
                atomicAdd(reinterpret_cast<float2*>(o0 + col),
                          make_float2(w0 * acc[mf][nf][0], w0 * acc[mf][nf][1]));
            if (o1)
                atomicAdd(reinterpret_cast<float2*>(o1 + col),
                          make_float2(w1 * acc[mf][nf][2], w1 * acc[mf][nf][3]));
        }
    }
}

// ---------------- launch ------------------------------------------------------
extern "C" void kernel_launch(void* const* d_in, const int* in_sizes, int n_in,
                              void* d_out, int out_size) {
    const float* x  = (const float*)d_in[0];   // [8192,1024]
    const float* gw = (const float*)d_in[1];   // [8,1024]
    const float* ew = (const float*)d_in[2];   // [8,1024,1024]
    float* out = (float*)d_out;                // [8192,1024]

    cudaFuncSetAttribute(moe_hmma_kernel,
                         cudaFuncAttributeMaxDynamicSharedMemorySize, SMEM_DYN);

    prep_kernel<<<NB_EW + NB_GATE, 256>>>((const float4*)x, (const float4*)ew,
                                          (float4*)out, gw);

    dim3 grid(HIDDEN / 128, NUM_TOKENS / 128, NUM_EXPERTS);
    moe_hmma_kernel<<<grid, 256, SMEM_DYN>>>(out);
}